// round 13
// baseline (speedup 1.0000x reference)
#include <cuda_runtime.h>
#include <cuda_bf16.h>
#include <math.h>

// ---------------------------------------------------------------------------
// WITRAN 2D-PSGMU encoder — mma.sync tf32, fragment-permuted operands.
// A fragments: direct LDG.128 from permuted global (L1 dedups warp reuse).
// B fragments: cp.async 3-stage smem ring.
//   B=32, R=24, Lorig=48, L=71, H=256, C=32, K=544, M=768
// ---------------------------------------------------------------------------

#define NB     32
#define RR_    24
#define LORIG  48
#define LL     71
#define MM     768
#define OFF1   27918336
#define OFF2   28311552

// linear fp32 carries (elementwise recurrence path)
__device__ __align__(1024) float g_h_row[2][MM * 256];
__device__ __align__(1024) float g_h_col[2][MM * 256];
// tf32 fragment-permuted carries (GEMM A), [12 blocks][8 chunks][2048]
__device__ __align__(1024) float g_hrp[2][12 * 16384];
__device__ __align__(1024) float g_hcp[2][12 * 16384];
// tf32 fragment-permuted weights: [8 u-tiles][17 chunks][6144]
__device__ __align__(1024) float g_wp[8 * 17 * 6144];
// tf32 fragment-permuted input: [(r*48+l)][1024]
__device__ __align__(1024) float g_xp[24 * 48 * 1024];

// smem: 3 ring buffers x 6144 floats (B only); epilogue stage reuses region
#define BBUF_F  6144
#define SMEM_BYTES (3 * BBUF_F * 4)
#define CS_ST   200

__device__ __forceinline__ float sigf(float x) {
    return __fdividef(1.0f, 1.0f + __expf(-x));
}
__device__ __forceinline__ float tanhf_(float x) {
    return 1.0f - __fdividef(2.0f, __expf(2.0f * x) + 1.0f);
}
__device__ __forceinline__ unsigned tf32c(float v) {
    unsigned r;
    asm("cvt.rna.tf32.f32 %0, %1;" : "=r"(r) : "f"(v));
    return r;
}

#define MMA_TF32(c, a, b0, b1) \
    asm volatile("mma.sync.aligned.m16n8k8.row.col.f32.tf32.tf32.f32 " \
        "{%0,%1,%2,%3},{%4,%5,%6,%7},{%8,%9},{%0,%1,%2,%3};" \
        : "+f"((c)[0]), "+f"((c)[1]), "+f"((c)[2]), "+f"((c)[3]) \
        : "r"((a).x), "r"((a).y), "r"((a).z), "r"((a).w), \
          "r"(b0), "r"(b1))

// fragment-permuted index inside one 64-row x 32-k chunk (2048 floats)
__device__ __forceinline__ int fragidx(int row64, int kk) {
    int group = row64 >> 4, p = row64 & 15;
    int q = kk >> 3, t = kk & 7, tg = t & 3, i2 = t >> 2;
    return group * 512 + q * 128 + (p & 7) * 16 + tg * 4 + (((p >> 3) & 1) | (i2 << 1));
}

// ---------------------------------------------------------------------------
__global__ void witran_init_kernel(const float* __restrict__ W,
                                   const float* __restrict__ input) {
    int idx0 = blockIdx.x * blockDim.x + threadIdx.x;
    int stride = gridDim.x * blockDim.x;
    for (int i = idx0; i < MM * 256; i += stride) {
        g_h_row[0][i] = 0.0f; g_h_col[0][i] = 0.0f;
        g_hrp[0][i] = 0.0f;   g_hcp[0][i] = 0.0f;
    }
    // W permute+convert: W[j][k], j = g*256 + v
    for (int idx = idx0; idx < 1536 * 544; idx += stride) {
        int j = idx / 544, k = idx - j * 544;
        int g = j >> 8, v = j & 255;
        int ut = v >> 5, nrow = (g << 5) + (v & 31);
        int c = k >> 5, kk = k & 31;
        int q = kk >> 3, t = kk & 7, tg = t & 3, i2 = t >> 2;
        g_wp[ut * 104448 + c * 6144 + q * 1536 + nrow * 8 + tg * 2 + i2] =
            __uint_as_float(tf32c(W[idx]));
    }
    // input permute+convert: input[b][l][r][c]
    for (int idx = idx0; idx < 32 * 48 * 24 * 32; idx += stride) {
        int c  = idx & 31;
        int t1 = idx >> 5;
        int r  = t1 % 24;
        int t2 = t1 / 24;
        int l  = t2 % 48;
        int b  = t2 / 48;
        int q = c >> 3, t = c & 7, tg = t & 3, i2 = t >> 2;
        int dst = (r * 48 + l) * 1024 + (b >> 4) * 512 + q * 128 +
                  (b & 7) * 16 + tg * 4 + (((b >> 3) & 1) | (i2 << 1));
        g_xp[dst] = __uint_as_float(tf32c(input[idx]));
    }
}

// ---------------------------------------------------------------------------
// grid (8, 12): bx = 32-unit tile, by = 64-row M tile. 256 threads,
// 8 warps in 2(M) x 4(N), warp tile 32 x 48.
__global__ void __launch_bounds__(256, 1)
witran_step_mma(int s, const float* __restrict__ Bp, float* __restrict__ out) {
    extern __shared__ float sm[];
    const unsigned sbase = (unsigned)__cvta_generic_to_shared(sm);

    const int tid  = threadIdx.x;
    const int wid  = tid >> 5, lane = tid & 31;
    const int g8   = lane >> 2, tg = lane & 3;
    const int wm   = wid & 1,  wn = wid >> 1;
    const int bx   = blockIdx.x, by = blockIdx.y;
    const int u0   = bx << 5;
    const int n0   = by << 6;
    const int cur  = s & 1, nxt = cur ^ 1;

    const float* wsrc = g_wp + bx * 104448;

    // ---- B prefetch: one 32-deep K chunk (192 x 32 = 6144 floats) --------
    auto prefetchB = [&](int c, int buf) {
        const unsigned dbase = sbase + buf * (BBUF_F * 4);
        const float* bsrc = wsrc + c * 6144;
#pragma unroll
        for (int i = 0; i < 6; ++i) {
            int u = tid + (i << 8);                 // 0..1535 16B units
            asm volatile("cp.async.cg.shared.global [%0], [%1], 16;"
                         :: "r"(dbase + u * 16), "l"(bsrc + u * 4));
        }
        asm volatile("cp.async.commit_group;");
    };

    // ---- A fragments: direct LDG.128 from fragment-permuted global -------
    const int afrag = g8 * 16 + tg * 4;
    const int aoff0 = (wm * 2) * 512 + afrag;       // smi=0
    const int aoff1 = aoff0 + 512;                  // smi=1
    const int rA = (by << 1) + wm;                  // r for x chunk (per warp)

    auto loadA = [&](int c, uint4* fa) {
        if (c < 16) {
            const float* base = (c < 8)
                ? (g_hrp[cur] + by * 16384 + c * 2048)
                : (g_hcp[cur] + by * 16384 + (c - 8) * 2048);
#pragma unroll
            for (int q = 0; q < 4; ++q) {
                fa[q * 2]     = *(const uint4*)(base + q * 128 + aoff0);
                fa[q * 2 + 1] = *(const uint4*)(base + q * 128 + aoff1);
            }
        } else {
            int l = s - rA;
            if (l >= 0 && l < LORIG) {
                const float* base = g_xp + (rA * 48 + l) * 1024;
#pragma unroll
                for (int q = 0; q < 4; ++q) {
                    fa[q * 2]     = *(const uint4*)(base + q * 128 + afrag);
                    fa[q * 2 + 1] = *(const uint4*)(base + 512 + q * 128 + afrag);
                }
            } else {
#pragma unroll
                for (int q = 0; q < 8; ++q) fa[q] = make_uint4(0, 0, 0, 0);
            }
        }
    };

    float c[2][6][4];
#pragma unroll
    for (int i = 0; i < 2; ++i)
#pragma unroll
        for (int j = 0; j < 6; ++j)
#pragma unroll
            for (int q = 0; q < 4; ++q) c[i][j][q] = 0.0f;

    uint4 areg[2][8];
    prefetchB(0, 0);
    prefetchB(1, 1);
    loadA(0, areg[0]);
    int buf = 0, pbuf = 2;
    for (int t = 0; t < 17; ++t) {
        if (t < 16) {
            loadA(t + 1, areg[(t + 1) & 1]);        // LDGs overlap B wait
            asm volatile("cp.async.wait_group 1;");
        } else {
            asm volatile("cp.async.wait_group 0;");
        }
        __syncthreads();
        if (t < 15) {
            prefetchB(t + 2, pbuf);
            if (++pbuf == 3) pbuf = 0;
        }
        const float* Bb = sm + buf * BBUF_F;
        if (++buf == 3) buf = 0;
        const uint4* A = areg[t & 1];
#pragma unroll
        for (int q = 0; q < 4; ++q) {
#pragma unroll
            for (int j8 = 0; j8 < 6; ++j8) {
                uint2 fb = *(const uint2*)(Bb + q * 1536 +
                                           (wn * 48 + j8 * 8 + g8) * 8 + tg * 2);
                MMA_TF32(c[0][j8], A[q * 2], fb.x, fb.y);
                MMA_TF32(c[1][j8], A[q * 2 + 1], fb.x, fb.y);
            }
        }
    }
    __syncthreads();

    // ---- stage gates to smem (reuse B ring), Cs[64][200] ------------------
    float* Cs = sm;
    {
        int row0 = (wm << 5) + g8;
        int colb = wn * 48 + (tg << 1);
#pragma unroll
        for (int smi = 0; smi < 2; ++smi)
#pragma unroll
            for (int j8 = 0; j8 < 6; ++j8) {
                int r = row0 + (smi << 4);
                int col = colb + (j8 << 3);
                *(float2*)&Cs[r * CS_ST + col] = make_float2(c[smi][j8][0], c[smi][j8][1]);
                *(float2*)&Cs[(r + 8) * CS_ST + col] = make_float2(c[smi][j8][2], c[smi][j8][3]);
            }
    }
    __syncthreads();

    // ---- fused recurrence epilogue ---------------------------------------
    const int v = tid & 31;
    const int m0 = tid >> 5;
    float bias[6];
#pragma unroll
    for (int g = 0; g < 6; ++g) bias[g] = Bp[(g << 8) + u0 + v];

#pragma unroll
    for (int i = 0; i < 8; ++i) {
        int m = m0 + (i << 3);
        int n = n0 + m;
        int r = n >> 5;
        float bm = (r <= s && s < RR_) ? 1.0f : 0.0f;
        float G[6];
#pragma unroll
        for (int g = 0; g < 6; ++g) G[g] = Cs[m * CS_ST + (g << 5) + v] + bm * bias[g];
        float u_row = sigf(G[0]), o_row = sigf(G[1]);
        float u_col = sigf(G[2]), o_col = sigf(G[3]);
        float i_row = tanhf_(G[4]), i_col = tanhf_(G[5]);
        float hro = g_h_row[cur][(n << 8) + u0 + v];
        float hco = g_h_col[cur][(n << 8) + u0 + v];
        float hr = tanhf_((1.0f - u_row) * hro + u_row * i_row) * o_row;
        float hc = tanhf_((1.0f - u_col) * hco + u_col * i_col) * o_col;

        size_t ob = ((size_t)n * LL + s) * 512 + u0 + v;
        out[ob]       = hr;
        out[ob + 256] = hc;
        g_h_row[nxt][(n << 8) + u0 + v] = hr;
        int n2 = n + NB; if (n2 >= MM) n2 -= MM;       // roll(h_col, +B)
        g_h_col[nxt][(n2 << 8) + u0 + v] = hc;

        // tf32 fragment-permuted carries for next step's GEMM A operand
        int fi = fragidx(m, v);
        g_hrp[nxt][by * 16384 + bx * 2048 + fi] = __uint_as_float(tf32c(hr));
        int blk2 = n2 >> 6, m2 = n2 & 63;
        g_hcp[nxt][blk2 * 16384 + bx * 2048 + fragidx(m2, v)] = __uint_as_float(tf32c(hc));
    }
}

// ---------------------------------------------------------------------------
__global__ void witran_gather_kernel(float* __restrict__ out) {
    int idx = blockIdx.x * blockDim.x + threadIdx.x;
    if (idx < 393216) {
        int k = idx & 255;
        int t = (idx >> 8) % LORIG;
        int b = idx / (LORIG * 256);
        out[OFF1 + idx] = out[((size_t)(736 + b) * LL + 23 + t) * 512 + 256 + k];
    } else if (idx < 589824) {
        int j = idx - 393216;
        int k = j & 255;
        int i = (j >> 8) % RR_;
        int b = j / (RR_ * 256);
        out[OFF2 + j] = out[((size_t)(i * NB + b) * LL + 47 + i) * 512 + k];
    }
}

// ---------------------------------------------------------------------------
extern "C" void kernel_launch(void* const* d_in, const int* in_sizes, int n_in,
                              void* d_out, int out_size) {
    const float* input = (const float*)d_in[0];
    const float* W     = (const float*)d_in[1];
    const float* Bp    = (const float*)d_in[2];
    float* out = (float*)d_out;

    cudaFuncSetAttribute(witran_step_mma,
                         cudaFuncAttributeMaxDynamicSharedMemorySize, SMEM_BYTES);

    witran_init_kernel<<<1024, 256>>>(W, input);
    for (int s = 0; s < LL; ++s) {
        witran_step_mma<<<dim3(8, 12), 256, SMEM_BYTES>>>(s, Bp, out);
    }
    witran_gather_kernel<<<2304, 256>>>(out);
}

// round 15
// speedup vs baseline: 1.7032x; 1.7032x over previous
#include <cuda_runtime.h>
#include <cuda_bf16.h>
#include <math.h>

// ---------------------------------------------------------------------------
// WITRAN 2D-PSGMU encoder — mma.sync tf32, fragment-permuted operands,
// bulk-TMA (cp.async.bulk + mbarrier) staging, 3-stage ring.
//   B=32, R=24, Lorig=48, L=71, H=256, C=32, K=544, M=768
// ---------------------------------------------------------------------------

#define NB     32
#define RR_    24
#define LORIG  48
#define LL     71
#define MM     768
#define OFF1   27918336
#define OFF2   28311552

// linear fp32 carries (elementwise recurrence path)
__device__ __align__(1024) float g_h_row[2][MM * 256];
__device__ __align__(1024) float g_h_col[2][MM * 256];
// tf32 fragment-permuted carries (GEMM A), [12 blocks][8 chunks][2048]
__device__ __align__(1024) float g_hrp[2][12 * 16384];
__device__ __align__(1024) float g_hcp[2][12 * 16384];
// tf32 fragment-permuted weights (B-paired): [8 u-tiles][17 chunks][6144]
__device__ __align__(1024) float g_wp[8 * 17 * 6144];
// tf32 fragment-permuted input: [(r*48+l)][1024] + 1 zero page
__device__ __align__(1024) float g_xp[(24 * 48 + 1) * 1024];

// smem: 3 stages x (A 2048 + B 6144) floats + 3 mbarriers
#define STAGE_F 8192
#define MBAR_OFF (3 * STAGE_F * 4)          // byte offset of mbar[0]
#define SMEM_BYTES (MBAR_OFF + 64)
#define CS_ST   200

__device__ __forceinline__ float sigf(float x) {
    return __fdividef(1.0f, 1.0f + __expf(-x));
}
__device__ __forceinline__ float tanhf_(float x) {
    return 1.0f - __fdividef(2.0f, __expf(2.0f * x) + 1.0f);
}
__device__ __forceinline__ unsigned tf32c(float v) {
    unsigned r;
    asm("cvt.rna.tf32.f32 %0, %1;" : "=r"(r) : "f"(v));
    return r;
}

#define MMA_TF32(c, a, b0, b1) \
    asm volatile("mma.sync.aligned.m16n8k8.row.col.f32.tf32.tf32.f32 " \
        "{%0,%1,%2,%3},{%4,%5,%6,%7},{%8,%9},{%0,%1,%2,%3};" \
        : "+f"((c)[0]), "+f"((c)[1]), "+f"((c)[2]), "+f"((c)[3]) \
        : "r"((a).x), "r"((a).y), "r"((a).z), "r"((a).w), \
          "r"(b0), "r"(b1))

// fragment-permuted index inside one 64-row x 32-k A chunk (2048 floats)
__device__ __forceinline__ int fragidx(int row64, int kk) {
    int group = row64 >> 4, p = row64 & 15;
    int q = kk >> 3, t = kk & 7, tg = t & 3, i2 = t >> 2;
    return group * 512 + q * 128 + (p & 7) * 16 + tg * 4 + (((p >> 3) & 1) | (i2 << 1));
}

// ---------------------------------------------------------------------------
__global__ void witran_init_kernel(const float* __restrict__ W,
                                   const float* __restrict__ input) {
    int idx0 = blockIdx.x * blockDim.x + threadIdx.x;
    int stride = gridDim.x * blockDim.x;
    for (int i = idx0; i < MM * 256; i += stride) {
        g_h_row[0][i] = 0.0f; g_h_col[0][i] = 0.0f;
        g_hrp[0][i] = 0.0f;   g_hcp[0][i] = 0.0f;
    }
    for (int i = idx0; i < 1024; i += stride)
        g_xp[24 * 48 * 1024 + i] = 0.0f;            // zero page
    // W permute+convert, B fragments paired (two j8 per 16B):
    for (int idx = idx0; idx < 1536 * 544; idx += stride) {
        int j = idx / 544, k = idx - j * 544;
        int g = j >> 8, v = j & 255;
        int ut = v >> 5;
        int nrow = (g << 5) + (v & 31);             // 0..191 inside u-tile
        int jj = nrow >> 3, g8i = nrow & 7;
        int c = k >> 5, kk = k & 31;
        int q = kk >> 3, t = kk & 7, tg = t & 3, i2 = t >> 2;
        g_wp[ut * 104448 + c * 6144 + q * 1536 + (jj >> 1) * 128 +
             g8i * 16 + tg * 4 + (jj & 1) * 2 + i2] =
            __uint_as_float(tf32c(W[idx]));
    }
    // input permute+convert: input[b][l][r][c] -> page (r*48+l)
    for (int idx = idx0; idx < 32 * 48 * 24 * 32; idx += stride) {
        int c  = idx & 31;
        int t1 = idx >> 5;
        int r  = t1 % 24;
        int t2 = t1 / 24;
        int l  = t2 % 48;
        int b  = t2 / 48;
        int q = c >> 3, t = c & 7, tg = t & 3, i2 = t >> 2;
        int dst = (r * 48 + l) * 1024 + (b >> 4) * 512 + q * 128 +
                  (b & 7) * 16 + tg * 4 + (((b >> 3) & 1) | (i2 << 1));
        g_xp[dst] = __uint_as_float(tf32c(input[idx]));
    }
}

// ---------------------------------------------------------------------------
// grid (8, 12): bx = 32-unit tile, by = 64-row M tile. 256 threads,
// 8 warps in 2(M) x 4(N), warp tile 32 x 48.
__global__ void __launch_bounds__(256, 1)
witran_step_mma(int s, const float* __restrict__ Bp, float* __restrict__ out) {
    extern __shared__ float sm[];
    const unsigned sbase = (unsigned)__cvta_generic_to_shared(sm);
    const unsigned mbase = sbase + MBAR_OFF;

    const int tid  = threadIdx.x;
    const int wid  = tid >> 5, lane = tid & 31;
    const int g8   = lane >> 2, tg = lane & 3;
    const int wm   = wid & 1,  wn = wid >> 1;
    const int bx   = blockIdx.x, by = blockIdx.y;
    const int u0   = bx << 5;
    const int n0   = by << 6;
    const int cur  = s & 1, nxt = cur ^ 1;

    const float* wsrc = g_wp + bx * 104448;
    const float* zpage = g_xp + 24 * 48 * 1024;

    if (tid == 0) {
#pragma unroll
        for (int i = 0; i < 3; ++i)
            asm volatile("mbarrier.init.shared.b64 [%0], %1;"
                         :: "r"(mbase + i * 8), "r"(1u) : "memory");
    }
    __syncthreads();

    // ---- bulk-TMA prefetch of one 32-deep K chunk into a ring stage ------
    auto prefetch = [&](int c, int stage) {
        const unsigned mb = mbase + stage * 8;
        const unsigned dA = sbase + stage * (STAGE_F * 4);
        const unsigned dB = dA + 2048 * 4;
        asm volatile("mbarrier.arrive.expect_tx.shared.b64 _, [%0], %1;"
                     :: "r"(mb), "r"(32768u) : "memory");
        asm volatile("cp.async.bulk.shared::cta.global.mbarrier::complete_tx::bytes"
                     " [%0], [%1], %2, [%3];"
                     :: "r"(dB), "l"(wsrc + c * 6144), "r"(24576u), "r"(mb) : "memory");
        if (c < 8) {
            asm volatile("cp.async.bulk.shared::cta.global.mbarrier::complete_tx::bytes"
                         " [%0], [%1], %2, [%3];"
                         :: "r"(dA), "l"(g_hrp[cur] + by * 16384 + c * 2048),
                            "r"(8192u), "r"(mb) : "memory");
        } else if (c < 16) {
            asm volatile("cp.async.bulk.shared::cta.global.mbarrier::complete_tx::bytes"
                         " [%0], [%1], %2, [%3];"
                         :: "r"(dA), "l"(g_hcp[cur] + by * 16384 + (c - 8) * 2048),
                            "r"(8192u), "r"(mb) : "memory");
        } else {
            int r0 = by * 2, l0 = s - r0;
            const float* s0 = (l0 >= 0 && l0 < LORIG) ? g_xp + (r0 * 48 + l0) * 1024 : zpage;
            int r1 = r0 + 1, l1 = s - r1;
            const float* s1 = (l1 >= 0 && l1 < LORIG) ? g_xp + (r1 * 48 + l1) * 1024 : zpage;
            asm volatile("cp.async.bulk.shared::cta.global.mbarrier::complete_tx::bytes"
                         " [%0], [%1], %2, [%3];"
                         :: "r"(dA), "l"(s0), "r"(4096u), "r"(mb) : "memory");
            asm volatile("cp.async.bulk.shared::cta.global.mbarrier::complete_tx::bytes"
                         " [%0], [%1], %2, [%3];"
                         :: "r"(dA + 4096), "l"(s1), "r"(4096u), "r"(mb) : "memory");
        }
    };

    auto mwait = [&](int stage, int phase) {
        asm volatile("{\n .reg .pred P;\n"
                     "LW%=:\n mbarrier.try_wait.parity.acquire.cta.shared::cta.b64 P, [%0], %1, 0x989680;\n"
                     " @P bra LD%=;\n bra LW%=;\nLD%=:\n}"
                     :: "r"(mbase + stage * 8), "r"((unsigned)phase) : "memory");
    };

    float c[2][6][4];
#pragma unroll
    for (int i = 0; i < 2; ++i)
#pragma unroll
        for (int j = 0; j < 6; ++j)
#pragma unroll
            for (int q = 0; q < 4; ++q) c[i][j][q] = 0.0f;

    if (tid == 0) { prefetch(0, 0); prefetch(1, 1); prefetch(2, 2); }

    const int afrag = g8 * 16 + tg * 4;
    for (int t = 0; t < 17; ++t) {
        const int stage = t % 3, phase = (t / 3) & 1;
        mwait(stage, phase);
        const float* Ab = sm + stage * STAGE_F;
        const float* Bb = Ab + 2048;
#pragma unroll
        for (int q = 0; q < 4; ++q) {
            uint4 fa0 = *(const uint4*)(Ab + (wm * 2) * 512 + q * 128 + afrag);
            uint4 fa1 = *(const uint4*)(Ab + (wm * 2 + 1) * 512 + q * 128 + afrag);
#pragma unroll
            for (int jp = 0; jp < 3; ++jp) {
                uint4 fb = *(const uint4*)(Bb + q * 1536 + (wn * 3 + jp) * 128 + afrag);
                MMA_TF32(c[0][2 * jp],     fa0, fb.x, fb.y);
                MMA_TF32(c[1][2 * jp],     fa1, fb.x, fb.y);
                MMA_TF32(c[0][2 * jp + 1], fa0, fb.z, fb.w);
                MMA_TF32(c[1][2 * jp + 1], fa1, fb.z, fb.w);
            }
        }
        __syncthreads();                       // all reads of this stage done
        if (t < 14 && tid == 0) prefetch(t + 3, stage);
    }

    // ---- stage gates to smem (reuse ring), Cs[64][200] --------------------
    float* Cs = sm;
    {
        int row0 = (wm << 5) + g8;
        int colb = wn * 48 + (tg << 1);
#pragma unroll
        for (int smi = 0; smi < 2; ++smi)
#pragma unroll
            for (int j8 = 0; j8 < 6; ++j8) {
                int r = row0 + (smi << 4);
                int col = colb + (j8 << 3);
                *(float2*)&Cs[r * CS_ST + col] = make_float2(c[smi][j8][0], c[smi][j8][1]);
                *(float2*)&Cs[(r + 8) * CS_ST + col] = make_float2(c[smi][j8][2], c[smi][j8][3]);
            }
    }
    __syncthreads();

    // ---- fused recurrence epilogue ---------------------------------------
    const int v = tid & 31;
    const int m0 = tid >> 5;
    float bias[6];
#pragma unroll
    for (int g = 0; g < 6; ++g) bias[g] = Bp[(g << 8) + u0 + v];

#pragma unroll
    for (int i = 0; i < 8; ++i) {
        int m = m0 + (i << 3);
        int n = n0 + m;
        int r = n >> 5;
        float bm = (r <= s && s < RR_) ? 1.0f : 0.0f;
        float G[6];
#pragma unroll
        for (int g = 0; g < 6; ++g) G[g] = Cs[m * CS_ST + (g << 5) + v] + bm * bias[g];
        float u_row = sigf(G[0]), o_row = sigf(G[1]);
        float u_col = sigf(G[2]), o_col = sigf(G[3]);
        float i_row = tanhf_(G[4]), i_col = tanhf_(G[5]);
        float hro = g_h_row[cur][(n << 8) + u0 + v];
        float hco = g_h_col[cur][(n << 8) + u0 + v];
        float hr = tanhf_((1.0f - u_row) * hro + u_row * i_row) * o_row;
        float hc = tanhf_((1.0f - u_col) * hco + u_col * i_col) * o_col;

        size_t ob = ((size_t)n * LL + s) * 512 + u0 + v;
        out[ob]       = hr;
        out[ob + 256] = hc;
        g_h_row[nxt][(n << 8) + u0 + v] = hr;
        int n2 = n + NB; if (n2 >= MM) n2 -= MM;       // roll(h_col, +B)
        g_h_col[nxt][(n2 << 8) + u0 + v] = hc;

        // tf32 fragment-permuted carries for next step's GEMM A operand
        int fi = fragidx(m, v);
        g_hrp[nxt][by * 16384 + bx * 2048 + fi] = __uint_as_float(tf32c(hr));
        int blk2 = n2 >> 6, m2 = n2 & 63;
        g_hcp[nxt][blk2 * 16384 + bx * 2048 + fragidx(m2, v)] = __uint_as_float(tf32c(hc));
    }
}

// ---------------------------------------------------------------------------
__global__ void witran_gather_kernel(float* __restrict__ out) {
    int idx = blockIdx.x * blockDim.x + threadIdx.x;
    if (idx < 393216) {
        int k = idx & 255;
        int t = (idx >> 8) % LORIG;
        int b = idx / (LORIG * 256);
        out[OFF1 + idx] = out[((size_t)(736 + b) * LL + 23 + t) * 512 + 256 + k];
    } else if (idx < 589824) {
        int j = idx - 393216;
        int k = j & 255;
        int i = (j >> 8) % RR_;
        int b = j / (RR_ * 256);
        out[OFF2 + j] = out[((size_t)(i * NB + b) * LL + 47 + i) * 512 + k];
    }
}

// ---------------------------------------------------------------------------
extern "C" void kernel_launch(void* const* d_in, const int* in_sizes, int n_in,
                              void* d_out, int out_size) {
    const float* input = (const float*)d_in[0];
    const float* W     = (const float*)d_in[1];
    const float* Bp    = (const float*)d_in[2];
    float* out = (float*)d_out;

    cudaFuncSetAttribute(witran_step_mma,
                         cudaFuncAttributeMaxDynamicSharedMemorySize, SMEM_BYTES);

    witran_init_kernel<<<1024, 256>>>(W, input);
    for (int s = 0; s < LL; ++s) {
        witran_step_mma<<<dim3(8, 12), 256, SMEM_BYTES>>>(s, Bp, out);
    }
    witran_gather_kernel<<<2304, 256>>>(out);
}

// round 17
// speedup vs baseline: 1.7480x; 1.0263x over previous
#include <cuda_runtime.h>
#include <cuda_bf16.h>
#include <math.h>

// ---------------------------------------------------------------------------
// WITRAN 2D-PSGMU encoder — persistent mma.sync tf32 kernel.
//   One launch, 96 resident CTAs, atomic grid barrier between steps,
//   bulk-TMA 5-stage ring with cross-step B prefetch (A issued post-barrier).
//   B=32, R=24, Lorig=48, L=71, H=256, C=32, K=544, M=768
// ---------------------------------------------------------------------------

#define NB     32
#define RR_    24
#define LORIG  48
#define LL     71
#define MM     768
#define OFF1   27918336
#define OFF2   28311552
#define NCTA   96

// linear fp32 carries (elementwise recurrence path)
__device__ __align__(1024) float g_h_row[2][MM * 256];
__device__ __align__(1024) float g_h_col[2][MM * 256];
// tf32 fragment-permuted carries (GEMM A), [12 blocks][8 chunks][2048]
__device__ __align__(1024) float g_hrp[2][12 * 16384];
__device__ __align__(1024) float g_hcp[2][12 * 16384];
// tf32 fragment-permuted weights (B-paired): [8 u-tiles][17 chunks][6144]
__device__ __align__(1024) float g_wp[8 * 17 * 6144];
// tf32 fragment-permuted input: [(r*48+l)][1024] + 1 zero page
__device__ __align__(1024) float g_xp[(24 * 48 + 1) * 1024];
// grid barrier counter
__device__ unsigned g_bar;

// smem: 5 stages x (A 2048 + B 6144) floats, then Cs 64x200, then mbars
#define NSTAGE   5
#define STAGE_F  8192
#define CS_OFF   (NSTAGE * STAGE_F)              // 40960 floats
#define CS_ST    200
#define MBAR_BYTE ((CS_OFF + 64 * CS_ST) * 4)    // 215040
#define SMEM_BYTES (MBAR_BYTE + 128)

__device__ __forceinline__ float sigf(float x) {
    return __fdividef(1.0f, 1.0f + __expf(-x));
}
__device__ __forceinline__ float tanhf_(float x) {
    return 1.0f - __fdividef(2.0f, __expf(2.0f * x) + 1.0f);
}
__device__ __forceinline__ unsigned tf32c(float v) {
    unsigned r;
    asm("cvt.rna.tf32.f32 %0, %1;" : "=r"(r) : "f"(v));
    return r;
}

#define MMA_TF32(c, a, b0, b1) \
    asm volatile("mma.sync.aligned.m16n8k8.row.col.f32.tf32.tf32.f32 " \
        "{%0,%1,%2,%3},{%4,%5,%6,%7},{%8,%9},{%0,%1,%2,%3};" \
        : "+f"((c)[0]), "+f"((c)[1]), "+f"((c)[2]), "+f"((c)[3]) \
        : "r"((a).x), "r"((a).y), "r"((a).z), "r"((a).w), \
          "r"(b0), "r"(b1))

// fragment-permuted index inside one 64-row x 32-k A chunk (2048 floats)
__device__ __forceinline__ int fragidx(int row64, int kk) {
    int group = row64 >> 4, p = row64 & 15;
    int q = kk >> 3, t = kk & 7, tg = t & 3, i2 = t >> 2;
    return group * 512 + q * 128 + (p & 7) * 16 + tg * 4 + (((p >> 3) & 1) | (i2 << 1));
}

// ---------------------------------------------------------------------------
__global__ void witran_init_kernel(const float* __restrict__ W,
                                   const float* __restrict__ input) {
    int idx0 = blockIdx.x * blockDim.x + threadIdx.x;
    int stride = gridDim.x * blockDim.x;
    if (idx0 == 0) g_bar = 0u;
    for (int i = idx0; i < MM * 256; i += stride) {
        g_h_row[0][i] = 0.0f; g_h_col[0][i] = 0.0f;
        g_hrp[0][i] = 0.0f;   g_hcp[0][i] = 0.0f;
    }
    for (int i = idx0; i < 1024; i += stride)
        g_xp[24 * 48 * 1024 + i] = 0.0f;            // zero page
    // W permute+convert, B fragments paired (two j8 per 16B)
    for (int idx = idx0; idx < 1536 * 544; idx += stride) {
        int j = idx / 544, k = idx - j * 544;
        int g = j >> 8, v = j & 255;
        int ut = v >> 5;
        int nrow = (g << 5) + (v & 31);
        int jj = nrow >> 3, g8i = nrow & 7;
        int c = k >> 5, kk = k & 31;
        int q = kk >> 3, t = kk & 7, tg = t & 3, i2 = t >> 2;
        g_wp[ut * 104448 + c * 6144 + q * 1536 + (jj >> 1) * 128 +
             g8i * 16 + tg * 4 + (jj & 1) * 2 + i2] =
            __uint_as_float(tf32c(W[idx]));
    }
    // input permute+convert: input[b][l][r][c] -> page (r*48+l)
    for (int idx = idx0; idx < 32 * 48 * 24 * 32; idx += stride) {
        int c  = idx & 31;
        int t1 = idx >> 5;
        int r  = t1 % 24;
        int t2 = t1 / 24;
        int l  = t2 % 48;
        int b  = t2 / 48;
        int q = c >> 3, t = c & 7, tg = t & 3, i2 = t >> 2;
        int dst = (r * 48 + l) * 1024 + (b >> 4) * 512 + q * 128 +
                  (b & 7) * 16 + tg * 4 + (((b >> 3) & 1) | (i2 << 1));
        g_xp[dst] = __uint_as_float(tf32c(input[idx]));
    }
}

// ---------------------------------------------------------------------------
// Persistent kernel: grid (8, 12), 256 threads, loops all 71 steps.
__global__ void __launch_bounds__(256, 1)
witran_persist(const float* __restrict__ Bp, float* __restrict__ out) {
    extern __shared__ float sm[];
    const unsigned sbase = (unsigned)__cvta_generic_to_shared(sm);
    const unsigned mbase = sbase + MBAR_BYTE;      // A mbars [0..4], B mbars [5..9]

    const int tid  = threadIdx.x;
    const int wid  = tid >> 5, lane = tid & 31;
    const int g8   = lane >> 2, tg = lane & 31 & 3;
    const int wm   = wid & 1,  wn = wid >> 1;
    const int bx   = blockIdx.x, by = blockIdx.y;
    const int u0   = bx << 5;
    const int n0   = by << 6;

    const float* wsrc  = g_wp + bx * 104448;
    const float* zpage = g_xp + 24 * 48 * 1024;

    if (tid == 0) {
#pragma unroll
        for (int i = 0; i < 2 * NSTAGE; ++i)
            asm volatile("mbarrier.init.shared.b64 [%0], %1;"
                         :: "r"(mbase + i * 8), "r"(1u) : "memory");
    }
    __syncthreads();

    // ---- issue helpers (tid 0 only) ---------------------------------------
    auto issueB = [&](int c, int st) {
        const unsigned mb = mbase + (NSTAGE + st) * 8;
        const unsigned dB = sbase + st * (STAGE_F * 4) + 2048 * 4;
        asm volatile("mbarrier.arrive.expect_tx.shared.b64 _, [%0], %1;"
                     :: "r"(mb), "r"(24576u) : "memory");
        asm volatile("cp.async.bulk.shared::cta.global.mbarrier::complete_tx::bytes"
                     " [%0], [%1], %2, [%3];"
                     :: "r"(dB), "l"(wsrc + c * 6144), "r"(24576u), "r"(mb) : "memory");
    };
    auto issueA = [&](int sstep, int c, int st) {
        const unsigned mb = mbase + st * 8;
        const unsigned dA = sbase + st * (STAGE_F * 4);
        const int scur = sstep & 1;
        asm volatile("mbarrier.arrive.expect_tx.shared.b64 _, [%0], %1;"
                     :: "r"(mb), "r"(8192u) : "memory");
        if (c < 8) {
            asm volatile("cp.async.bulk.shared::cta.global.mbarrier::complete_tx::bytes"
                         " [%0], [%1], %2, [%3];"
                         :: "r"(dA), "l"(g_hrp[scur] + by * 16384 + c * 2048),
                            "r"(8192u), "r"(mb) : "memory");
        } else if (c < 16) {
            asm volatile("cp.async.bulk.shared::cta.global.mbarrier::complete_tx::bytes"
                         " [%0], [%1], %2, [%3];"
                         :: "r"(dA), "l"(g_hcp[scur] + by * 16384 + (c - 8) * 2048),
                            "r"(8192u), "r"(mb) : "memory");
        } else {
            int r0 = by * 2, l0 = sstep - r0;
            const float* s0 = (l0 >= 0 && l0 < LORIG) ? g_xp + (r0 * 48 + l0) * 1024 : zpage;
            int r1 = r0 + 1, l1 = sstep - r1;
            const float* s1 = (l1 >= 0 && l1 < LORIG) ? g_xp + (r1 * 48 + l1) * 1024 : zpage;
            asm volatile("cp.async.bulk.shared::cta.global.mbarrier::complete_tx::bytes"
                         " [%0], [%1], %2, [%3];"
                         :: "r"(dA), "l"(s0), "r"(4096u), "r"(mb) : "memory");
            asm volatile("cp.async.bulk.shared::cta.global.mbarrier::complete_tx::bytes"
                         " [%0], [%1], %2, [%3];"
                         :: "r"(dA + 4096), "l"(s1), "r"(4096u), "r"(mb) : "memory");
        }
    };
    auto mwait = [&](int st, int phase) {
        asm volatile("{\n .reg .pred P;\n"
                     "LA%=:\n mbarrier.try_wait.parity.acquire.cta.shared::cta.b64 P, [%0], %2, 0x989680;\n"
                     " @P bra LB%=;\n bra LA%=;\n"
                     "LB%=:\n mbarrier.try_wait.parity.acquire.cta.shared::cta.b64 P, [%1], %2, 0x989680;\n"
                     " @P bra LD%=;\n bra LB%=;\nLD%=:\n}"
                     :: "r"(mbase + st * 8), "r"(mbase + (NSTAGE + st) * 8),
                        "r"((unsigned)phase) : "memory");
    };

    // prime pipeline: chunks 0..4 of step 0
    if (tid == 0) {
#pragma unroll
        for (int f = 0; f < NSTAGE; ++f) { issueB(f, f); issueA(0, f, f); }
    }

    const int v = tid & 31;
    const int m0 = tid >> 5;
    float bias[6];
#pragma unroll
    for (int g = 0; g < 6; ++g) bias[g] = Bp[(g << 8) + u0 + v];

    const int afrag = g8 * 16 + tg * 4;
    float* Cs = sm + CS_OFF;
    int cstage = 0, cphase = 0;

    for (int s = 0; s < LL; ++s) {
        const int cur = s & 1, nxt = cur ^ 1;

        float c[2][6][4];
#pragma unroll
        for (int i = 0; i < 2; ++i)
#pragma unroll
            for (int j = 0; j < 6; ++j)
#pragma unroll
                for (int q = 0; q < 4; ++q) c[i][j][q] = 0.0f;

        for (int t = 0; t < 17; ++t) {
            mwait(cstage, cphase);
            const float* Ab = sm + cstage * STAGE_F;
            const float* Bb = Ab + 2048;
#pragma unroll
            for (int q = 0; q < 4; ++q) {
                uint4 fa0 = *(const uint4*)(Ab + (wm * 2) * 512 + q * 128 + afrag);
                uint4 fa1 = *(const uint4*)(Ab + (wm * 2 + 1) * 512 + q * 128 + afrag);
#pragma unroll
                for (int jp = 0; jp < 3; ++jp) {
                    uint4 fb = *(const uint4*)(Bb + q * 1536 + (wn * 3 + jp) * 128 + afrag);
                    MMA_TF32(c[0][2 * jp],     fa0, fb.x, fb.y);
                    MMA_TF32(c[1][2 * jp],     fa1, fb.x, fb.y);
                    MMA_TF32(c[0][2 * jp + 1], fa0, fb.z, fb.w);
                    MMA_TF32(c[1][2 * jp + 1], fa1, fb.z, fb.w);
                }
            }
            __syncthreads();                     // stage fully consumed
            if (tid == 0) {
                if (t < 12) {                    // next chunk of this step
                    int cc = t + 5;
                    int st = (s * 17 + cc) % NSTAGE;
                    issueB(cc, st); issueA(s, cc, st);
                } else if (s + 1 < LL) {         // B-only for next step
                    issueB(t - 12, ((s + 1) * 17 + (t - 12)) % NSTAGE);
                }
            }
            if (++cstage == NSTAGE) { cstage = 0; cphase ^= 1; }
        }

        // ---- stage gates to Cs --------------------------------------------
        {
            int row0 = (wm << 5) + g8;
            int colb = wn * 48 + (tg << 1);
#pragma unroll
            for (int smi = 0; smi < 2; ++smi)
#pragma unroll
                for (int j8 = 0; j8 < 6; ++j8) {
                    int r = row0 + (smi << 4);
                    int col = colb + (j8 << 3);
                    *(float2*)&Cs[r * CS_ST + col] =
                        make_float2(c[smi][j8][0], c[smi][j8][1]);
                    *(float2*)&Cs[(r + 8) * CS_ST + col] =
                        make_float2(c[smi][j8][2], c[smi][j8][3]);
                }
        }
        __syncthreads();

        // ---- fused recurrence epilogue ------------------------------------
#pragma unroll
        for (int i = 0; i < 8; ++i) {
            int m = m0 + (i << 3);
            int n = n0 + m;
            int r = n >> 5;
            float bm = (r <= s && s < RR_) ? 1.0f : 0.0f;
            float G[6];
#pragma unroll
            for (int g = 0; g < 6; ++g)
                G[g] = Cs[m * CS_ST + (g << 5) + v] + bm * bias[g];
            float u_row = sigf(G[0]), o_row = sigf(G[1]);
            float u_col = sigf(G[2]), o_col = sigf(G[3]);
            float i_row = tanhf_(G[4]), i_col = tanhf_(G[5]);
            float hro = g_h_row[cur][(n << 8) + u0 + v];
            float hco = g_h_col[cur][(n << 8) + u0 + v];
            float hr = tanhf_((1.0f - u_row) * hro + u_row * i_row) * o_row;
            float hc = tanhf_((1.0f - u_col) * hco + u_col * i_col) * o_col;

            size_t ob = ((size_t)n * LL + s) * 512 + u0 + v;
            out[ob]       = hr;
            out[ob + 256] = hc;
            g_h_row[nxt][(n << 8) + u0 + v] = hr;
            int n2 = n + NB; if (n2 >= MM) n2 -= MM;   // roll(h_col, +B)
            g_h_col[nxt][(n2 << 8) + u0 + v] = hc;

            int fi = fragidx(m, v);
            g_hrp[nxt][by * 16384 + bx * 2048 + fi] = __uint_as_float(tf32c(hr));
            int blk2 = n2 >> 6, m2 = n2 & 63;
            g_hcp[nxt][blk2 * 16384 + bx * 2048 + fragidx(m2, v)] =
                __uint_as_float(tf32c(hc));
        }

        // ---- grid barrier + post-barrier A issue --------------------------
        if (s + 1 < LL) {
            __syncthreads();
            __threadfence();
            __syncthreads();
            if (tid == 0) {
                unsigned target = (unsigned)NCTA * (unsigned)(s + 1);
                asm volatile("red.release.gpu.global.add.u32 [%0], %1;"
                             :: "l"(&g_bar), "r"(1u) : "memory");
                unsigned vv;
                do {
                    asm volatile("nanosleep.u32 64;");
                    asm volatile("ld.acquire.gpu.global.u32 %0, [%1];"
                                 : "=r"(vv) : "l"(&g_bar));
                } while (vv < target);
                asm volatile("fence.proxy.async;" ::: "memory");
#pragma unroll
                for (int fs = 0; fs < NSTAGE; ++fs)
                    issueA(s + 1, fs, ((s + 1) * 17 + fs) % NSTAGE);
            }
            __syncthreads();
        }
    }
}

// ---------------------------------------------------------------------------
__global__ void witran_gather_kernel(float* __restrict__ out) {
    int idx = blockIdx.x * blockDim.x + threadIdx.x;
    if (idx < 393216) {
        int k = idx & 255;
        int t = (idx >> 8) % LORIG;
        int b = idx / (LORIG * 256);
        out[OFF1 + idx] = out[((size_t)(736 + b) * LL + 23 + t) * 512 + 256 + k];
    } else if (idx < 589824) {
        int j = idx - 393216;
        int k = j & 255;
        int i = (j >> 8) % RR_;
        int b = j / (RR_ * 256);
        out[OFF2 + j] = out[((size_t)(i * NB + b) * LL + 47 + i) * 512 + k];
    }
}

// ---------------------------------------------------------------------------
extern "C" void kernel_launch(void* const* d_in, const int* in_sizes, int n_in,
                              void* d_out, int out_size) {
    const float* input = (const float*)d_in[0];
    const float* W     = (const float*)d_in[1];
    const float* Bp    = (const float*)d_in[2];
    float* out = (float*)d_out;

    cudaFuncSetAttribute(witran_persist,
                         cudaFuncAttributeMaxDynamicSharedMemorySize, SMEM_BYTES);

    witran_init_kernel<<<1024, 256>>>(W, input);
    witran_persist<<<dim3(8, 12), 256, SMEM_BYTES>>>(Bp, out);
    witran_gather_kernel<<<2304, 256>>>(out);
}